// round 8
// baseline (speedup 1.0000x reference)
#include <cuda_runtime.h>
#include <math.h>

// RoI max pooling (Caffe-style), bit-matching the JAX/XLA reference.
//   x    : [B=2, C=128, H=64, W=64] fp32
//   rois : [N=256, 5]  (batch_idx, x1, y1, x2, y2) image coords
//   out  : [N, C, 7, 7] fp32
//
// R8: R7 profile showed nothing saturated (L1 10%, issue 40%) -> pure
// latency exposure, MLP~1 in the gather loop. Fix: 2 rows x 4 cols of
// predicated loads per iteration with two independent accumulators, so
// ptxas front-batches up to 8 LDGs per stall point (MLP ~8).
//
// CRITICAL (bit-exactness): XLA rewrites `roi / 7` into `roi * fl32(1/7)`.
// Must use the same reciprocal multiply or floor/ceil bin boundaries shift
// by 1 ulp on 7-divisible roi extents (caused rel_err 9.6e-2 in R1/R3).

#define B_  2
#define C_  128
#define H_  64
#define W_  64
#define S_  (H_ * W_)        // 4096
#define N_  256
#define OUTH_ 7
#define OUTW_ 7
#define NB_  (OUTH_ * OUTW_) // 49
#define SCALE_ (1.0f / 16.0f)
#define RCP7_  (1.0f / 7.0f) // fp32 RN: 0x3E124925

// channels-last scratch copy of x (static device global -> no allocation), 4 MB
__device__ float g_xt[B_ * S_ * C_];   // [b][h][w][c]

// ---------------------------------------------------------------- transpose
__global__ void transpose_kernel(const float* __restrict__ x) {
    __shared__ float t[32][33];
    const int b  = blockIdx.z;
    const int s0 = blockIdx.x * 32;
    const int c0 = blockIdx.y * 32;
    #pragma unroll
    for (int i = 0; i < 4; ++i) {
        const int c = c0 + threadIdx.y + i * 8;
        t[threadIdx.y + i * 8][threadIdx.x] =
            x[((size_t)b * C_ + c) * S_ + s0 + threadIdx.x];
    }
    __syncthreads();
    #pragma unroll
    for (int i = 0; i < 4; ++i) {
        const int s = s0 + threadIdx.y + i * 8;
        g_xt[((size_t)b * S_ + s) * C_ + c0 + threadIdx.x] =
            t[threadIdx.x][threadIdx.y + i * 8];
    }
}

// --------------------------------------------------------------------- pool
// Block = (ph, n). 256 threads = 8 warps.
// Warp w: channels (w&3)*32 + lane; bins pw = (w>>2), (w>>2)+2, ...
// Lanes share the bin -> uniform loops, each gather = one 128B line.
__global__ void roi_pool_kernel(const float* __restrict__ rois,
                                float* __restrict__ out) {
    __shared__ int4  sb[OUTW_];           // clamped {hs, he, ws, we} per pw
    __shared__ int   sbidx;
    __shared__ float tile[OUTW_ * 129];   // [pw][c], padded rows

    const int ph = blockIdx.x;
    const int n  = blockIdx.y;
    const int t  = threadIdx.x;

    if (t < OUTW_) {
        const int pw = t;
        const float* r = rois + n * 5;
        const int xs = (int)rintf(r[1] * SCALE_);
        const int ys = (int)rintf(r[2] * SCALE_);
        const int xe = (int)rintf(r[3] * SCALE_);
        const int ye = (int)rintf(r[4] * SCALE_);
        const float roi_w = (float)max(xe - xs + 1, 1);
        const float roi_h = (float)max(ye - ys + 1, 1);
        // match XLA's divide -> multiply-by-reciprocal rewrite exactly
        const float bin_h = __fmul_rn(roi_h, RCP7_);
        const float bin_w = __fmul_rn(roi_w, RCP7_);
        int hs = (int)floorf(__fmul_rn((float)ph, bin_h)) + ys;
        int he = (int)ceilf(__fmul_rn((float)ph + 1.0f, bin_h)) + ys;
        int ws = (int)floorf(__fmul_rn((float)pw, bin_w)) + xs;
        int we = (int)ceilf(__fmul_rn((float)pw + 1.0f, bin_w)) + xs;
        hs = min(max(hs, 0), H_);
        he = min(max(he, 0), H_);
        ws = min(max(ws, 0), W_);
        we = min(max(we, 0), W_);
        sb[pw] = make_int4(hs, he, ws, we);
        if (t == 0) sbidx = (int)r[0];
    }
    __syncthreads();

    const int warpid = t >> 5;
    const int c      = ((warpid & 3) << 5) + (t & 31);
    const float* base = g_xt + (size_t)sbidx * (S_ * C_) + c;

    for (int pw = (warpid >> 2); pw < OUTW_; pw += 2) {
        const int4 b = sb[pw];   // uniform across the warp
        float m0 = -INFINITY, m1 = -INFINITY;
        for (int h = b.x; h < b.y; h += 2) {
            const float* r0 = base + (size_t)(h * W_) * C_;
            const bool has1 = (h + 1) < b.y;
            const float* r1 = has1 ? r0 + (size_t)W_ * C_ : r0;
            for (int w = b.z; w < b.w; w += 4) {
                // up to 8 independent predicated loads in flight
                #pragma unroll
                for (int j = 0; j < 4; ++j) {
                    if (w + j < b.w) {
                        const float v0 = __ldg(r0 + (size_t)(w + j) * C_);
                        const float v1 = has1 ? __ldg(r1 + (size_t)(w + j) * C_) : -INFINITY;
                        m0 = fmaxf(m0, v0);
                        m1 = fmaxf(m1, v1);
                    }
                }
            }
        }
        const float m = fmaxf(m0, m1);
        const bool empty = (b.y <= b.x) || (b.w <= b.z);
        tile[pw * 129 + c] = empty ? 0.0f : m;
    }
    __syncthreads();

    // near-coalesced writeback: out[n][c][ph*7 + pw]
    float* outn = out + (size_t)n * (C_ * NB_) + ph * OUTW_;
    for (int o = t; o < C_ * OUTW_; o += 256) {
        const int co = o / OUTW_;
        const int pwo = o - co * OUTW_;
        outn[(size_t)co * NB_ + pwo] = tile[pwo * 129 + co];
    }
}

extern "C" void kernel_launch(void* const* d_in, const int* in_sizes, int n_in,
                              void* d_out, int out_size) {
    const float* x    = (const float*)d_in[0];
    const float* rois = (const float*)d_in[1];
    float* out = (float*)d_out;

    transpose_kernel<<<dim3(S_ / 32, C_ / 32, B_), dim3(32, 8)>>>(x);
    roi_pool_kernel<<<dim3(OUTH_, N_), 256>>>(rois, out);
}

// round 9
// speedup vs baseline: 1.3960x; 1.3960x over previous
#include <cuda_runtime.h>
#include <math.h>

// RoI max pooling (Caffe-style), bit-matching the JAX/XLA reference.
//   x    : [B=2, C=128, H=64, W=64] fp32
//   rois : [N=256, 5]  (batch_idx, x1, y1, x2, y2) image coords
//   out  : [N, C, 7, 7] fp32
//
// R9: back to the R4 champion structure (1 thread / output element, 1.6M
// threads, NCHW, coalesced stores) — empirically T scales with the serial
// dependent-load chain per warp once warp count saturates. Shrink the chain
// and the wavefront count together: gather each bin row as 1-2 aligned
// float4 loads (vs 3-4 scalar), with 4 independent max accumulators and
// per-element mask selects.
//
// CRITICAL (bit-exactness): XLA rewrites `roi / 7` into `roi * fl32(1/7)`.
// Must use the same reciprocal multiply or floor/ceil bin boundaries shift
// by 1 ulp on 7-divisible roi extents (caused rel_err 9.6e-2 in R1/R3).

#define B_  2
#define C_  128
#define H_  64
#define W_  64
#define W4_ (W_ / 4)         // 16 float4 per row
#define N_  256
#define OUTH_ 7
#define OUTW_ 7
#define SCALE_ (1.0f / 16.0f)
#define RCP7_  (1.0f / 7.0f) // fp32 RN: 0x3E124925

__global__ void roi_pool_kernel(const float* __restrict__ x,
                                const float* __restrict__ rois,
                                float* __restrict__ out) {
    const int total = N_ * C_ * OUTH_ * OUTW_;
    int idx = blockIdx.x * blockDim.x + threadIdx.x;
    if (idx >= total) return;

    const int pw = idx % OUTW_;
    const int ph = (idx / OUTW_) % OUTH_;
    const int c  = (idx / (OUTW_ * OUTH_)) % C_;
    const int n  =  idx / (OUTW_ * OUTH_ * C_);

    // roi params (L1-resident; redundancy proven non-binding in R5)
    const float* r = rois + n * 5;
    const int bidx = (int)r[0];
    const int xs = (int)rintf(r[1] * SCALE_);
    const int ys = (int)rintf(r[2] * SCALE_);
    const int xe = (int)rintf(r[3] * SCALE_);
    const int ye = (int)rintf(r[4] * SCALE_);

    const float roi_w = (float)max(xe - xs + 1, 1);
    const float roi_h = (float)max(ye - ys + 1, 1);
    // match XLA's divide -> multiply-by-reciprocal rewrite exactly
    const float bin_h = __fmul_rn(roi_h, RCP7_);
    const float bin_w = __fmul_rn(roi_w, RCP7_);

    int hs = (int)floorf(__fmul_rn((float)ph, bin_h)) + ys;
    int he = (int)ceilf(__fmul_rn((float)ph + 1.0f, bin_h)) + ys;
    int ws = (int)floorf(__fmul_rn((float)pw, bin_w)) + xs;
    int we = (int)ceilf(__fmul_rn((float)pw + 1.0f, bin_w)) + xs;
    hs = min(max(hs, 0), H_);
    he = min(max(he, 0), H_);
    ws = min(max(ws, 0), W_);
    we = min(max(we, 0), W_);

    const bool empty = (he <= hs) || (we <= ws);

    const float4* plane4 =
        (const float4*)(x + ((size_t)bidx * C_ + c) * (H_ * W_));

    float m0 = -INFINITY, m1 = -INFINITY, m2 = -INFINITY, m3 = -INFINITY;

    if (!empty) {
        const int q0 = ws >> 2;
        const int q1 = (we - 1) >> 2;   // inclusive
        for (int h = hs; h < he; ++h) {
            const float4* row4 = plane4 + h * W4_;
            for (int q = q0; q <= q1; ++q) {
                const float4 v = __ldg(row4 + q);
                const int wb = q << 2;
                // per-element window mask (-INF outside [ws, we))
                m0 = fmaxf(m0, (wb + 0 >= ws && wb + 0 < we) ? v.x : -INFINITY);
                m1 = fmaxf(m1, (wb + 1 >= ws && wb + 1 < we) ? v.y : -INFINITY);
                m2 = fmaxf(m2, (wb + 2 >= ws && wb + 2 < we) ? v.z : -INFINITY);
                m3 = fmaxf(m3, (wb + 3 >= ws && wb + 3 < we) ? v.w : -INFINITY);
            }
        }
    }

    const float m = fmaxf(fmaxf(m0, m1), fmaxf(m2, m3));
    out[idx] = empty ? 0.0f : m;
}

extern "C" void kernel_launch(void* const* d_in, const int* in_sizes, int n_in,
                              void* d_out, int out_size) {
    const float* x    = (const float*)d_in[0];
    const float* rois = (const float*)d_in[1];
    float* out = (float*)d_out;

    const int total = N_ * C_ * OUTH_ * OUTW_;
    const int threads = 256;
    const int blocks = (total + threads - 1) / threads;
    roi_pool_kernel<<<blocks, threads>>>(x, rois, out);
}

// round 10
// speedup vs baseline: 2.1542x; 1.5431x over previous
#include <cuda_runtime.h>
#include <math.h>

// RoI max pooling (Caffe-style), bit-matching the JAX/XLA reference.
//   x    : [B=2, C=128, H=64, W=64] fp32
//   rois : [N=256, 5]  (batch_idx, x1, y1, x2, y2) image coords
//   out  : [N, C, 7, 7] fp32
//
// R10: R9 showed float4 gathers fix the wavefront pressure (L1 68->37%)
// but per-(h,q) window masks made it ALU-bound (alu 63%). Masks depend
// only on q, not h -> swap loops (q outer, h inner): unmasked elementwise
// float4 max across rows (4 FMNMX/load), apply the mask ONCE per q after
// the h-loop. 4x less ALU in the hot loop, identical load stream.
//
// CRITICAL (bit-exactness): XLA rewrites `roi / 7` into `roi * fl32(1/7)`.
// Must use the same reciprocal multiply or floor/ceil bin boundaries shift
// by 1 ulp on 7-divisible roi extents (caused rel_err 9.6e-2 in R1/R3).

#define B_  2
#define C_  128
#define H_  64
#define W_  64
#define W4_ (W_ / 4)         // 16 float4 per row
#define N_  256
#define OUTH_ 7
#define OUTW_ 7
#define SCALE_ (1.0f / 16.0f)
#define RCP7_  (1.0f / 7.0f) // fp32 RN: 0x3E124925

__global__ void roi_pool_kernel(const float* __restrict__ x,
                                const float* __restrict__ rois,
                                float* __restrict__ out) {
    const int total = N_ * C_ * OUTH_ * OUTW_;
    int idx = blockIdx.x * blockDim.x + threadIdx.x;
    if (idx >= total) return;

    const int pw = idx % OUTW_;
    const int ph = (idx / OUTW_) % OUTH_;
    const int c  = (idx / (OUTW_ * OUTH_)) % C_;
    const int n  =  idx / (OUTW_ * OUTH_ * C_);

    // roi params (L1-resident; redundancy proven non-binding in R5)
    const float* r = rois + n * 5;
    const int bidx = (int)r[0];
    const int xs = (int)rintf(r[1] * SCALE_);
    const int ys = (int)rintf(r[2] * SCALE_);
    const int xe = (int)rintf(r[3] * SCALE_);
    const int ye = (int)rintf(r[4] * SCALE_);

    const float roi_w = (float)max(xe - xs + 1, 1);
    const float roi_h = (float)max(ye - ys + 1, 1);
    // match XLA's divide -> multiply-by-reciprocal rewrite exactly
    const float bin_h = __fmul_rn(roi_h, RCP7_);
    const float bin_w = __fmul_rn(roi_w, RCP7_);

    int hs = (int)floorf(__fmul_rn((float)ph, bin_h)) + ys;
    int he = (int)ceilf(__fmul_rn((float)ph + 1.0f, bin_h)) + ys;
    int ws = (int)floorf(__fmul_rn((float)pw, bin_w)) + xs;
    int we = (int)ceilf(__fmul_rn((float)pw + 1.0f, bin_w)) + xs;
    hs = min(max(hs, 0), H_);
    he = min(max(he, 0), H_);
    ws = min(max(ws, 0), W_);
    we = min(max(we, 0), W_);

    const bool empty = (he <= hs) || (we <= ws);

    const float4* plane4 =
        (const float4*)(x + ((size_t)bidx * C_ + c) * (H_ * W_));

    float m = -INFINITY;

    if (!empty) {
        const int q0 = ws >> 2;
        const int q1 = (we - 1) >> 2;   // inclusive
        for (int q = q0; q <= q1; ++q) {
            // unmasked column-wise max over all rows: 1 LDG + 4 FMNMX per h
            float4 a = make_float4(-INFINITY, -INFINITY, -INFINITY, -INFINITY);
            const float4* p = plane4 + hs * W4_ + q;
            for (int h = hs; h < he; ++h, p += W4_) {
                const float4 v = __ldg(p);
                a.x = fmaxf(a.x, v.x);
                a.y = fmaxf(a.y, v.y);
                a.z = fmaxf(a.z, v.z);
                a.w = fmaxf(a.w, v.w);
            }
            // apply the window mask once per q
            const int wb = q << 2;
            if (wb + 0 >= ws && wb + 0 < we) m = fmaxf(m, a.x);
            if (wb + 1 >= ws && wb + 1 < we) m = fmaxf(m, a.y);
            if (wb + 2 >= ws && wb + 2 < we) m = fmaxf(m, a.z);
            if (wb + 3 >= ws && wb + 3 < we) m = fmaxf(m, a.w);
        }
    }

    out[idx] = empty ? 0.0f : m;
}

extern "C" void kernel_launch(void* const* d_in, const int* in_sizes, int n_in,
                              void* d_out, int out_size) {
    const float* x    = (const float*)d_in[0];
    const float* rois = (const float*)d_in[1];
    float* out = (float*)d_out;

    const int total = N_ * C_ * OUTH_ * OUTW_;
    const int threads = 256;
    const int blocks = (total + threads - 1) / threads;
    roi_pool_kernel<<<blocks, threads>>>(x, rois, out);
}